// round 6
// baseline (speedup 1.0000x reference)
#include <cuda_runtime.h>
#include <cuda_bf16.h>
#include <cstdint>
#include <math.h>

#define BATCH 4
#define DIM   128
#define NPTS  4096
#define NB    (BATCH*NPTS)
#define MC    64            // m-chunks
#define MPER  64            // m per chunk
#define NBLK  (MC*BATCH)    // 256
#define INV_T 14.285714285714286f

// bf16 tile row stride: 64 m + 8 pad = 72 bf16 = 144 B (conflict-free LDSM)
#define BSTRIDE 144

// ---- device scratch (no allocations allowed) ----
__device__ uint32_t g_gpart[4194304];      // bf16x2 gram partials, 16.8 MB
__device__ float g_spart[2*BATCH*MC*DIM];  // per-d column-sum partials
__device__ float g_dgpart[NBLK];
__device__ float g_dg2part[NBLK];
__device__ float g_fpart[BATCH*32];
__device__ float g_s1[BATCH];
__device__ unsigned int g_ctr;             // zero-init; reset by finisher

// =============================== PTX helpers ===============================
__device__ __forceinline__ uint32_t smem_u32(const void* p) {
    uint32_t a;
    asm("{ .reg .u64 t; cvta.to.shared.u64 t, %1; cvt.u32.u64 %0, t; }"
        : "=r"(a) : "l"(p));
    return a;
}
__device__ __forceinline__ void ldsm_x4(uint32_t* r, uint32_t addr) {
    asm volatile("ldmatrix.sync.aligned.m8n8.x4.shared.b16 {%0,%1,%2,%3}, [%4];"
        : "=r"(r[0]), "=r"(r[1]), "=r"(r[2]), "=r"(r[3]) : "r"(addr));
}
__device__ __forceinline__ void mma_bf16(float* c, const uint32_t* a,
                                         uint32_t b0, uint32_t b1) {
    asm volatile("mma.sync.aligned.m16n8k16.row.col.f32.bf16.bf16.f32 "
        "{%0,%1,%2,%3}, {%4,%5,%6,%7}, {%8,%9}, {%0,%1,%2,%3};"
        : "+f"(c[0]), "+f"(c[1]), "+f"(c[2]), "+f"(c[3])
        : "r"(a[0]), "r"(a[1]), "r"(a[2]), "r"(a[3]), "r"(b0), "r"(b1));
}
__device__ __forceinline__ uint32_t hmul2u(uint32_t a, uint32_t b) {
    uint32_t r;
    asm("mul.bf16x2 %0, %1, %2;" : "=r"(r) : "r"(a), "r"(b));
    return r;
}
__device__ __forceinline__ uint32_t bf2u(__nv_bfloat162 v) {
    return *(uint32_t*)&v;
}

// smem byte layout (total 37952 B; scratch rq/rk/rd ALIASES the tile region —
// scratch is dead before phase 3 writes the tiles)
#define SB_QB   0            // 18432
#define SB_KB   18432        // 18432  (tiles end at 36864)
#define SB_RQ   0            // alias: 32 dgroups x 64 m x 4B = 8192
#define SB_RK   8192
#define SB_RD   16384        // ends 24576 < 36864 ok
#define SB_NS   36864        // nsum 3*64*4 = 768
#define SB_IQ2  37632        // 32 u32
#define SB_IK2  37760        // 32 u32
#define SB_SCR  37888        // 16 floats
#define SB_TOTAL 37952

// ===========================================================================
// k_main: 512 thr, grid (64,4). Per (chunk,b): single global read of
// 128d x 64m q/k; L1 norms + q.k in flight; HMUL2 normalize -> bf16 tiles;
// each warp runs two 16x64 gram jobs (one per gram) via mma.sync; bf16
// partials out.
// ===========================================================================
__global__ __launch_bounds__(512, 2) void k_main(const float* __restrict__ q,
                                                 const float* __restrict__ k) {
    extern __shared__ char smc[];
    char*  qb  = smc + SB_QB;
    char*  kb  = smc + SB_KB;
    float* rq  = (float*)(smc + SB_RQ);
    float* rk  = (float*)(smc + SB_RK);
    float* rd  = (float*)(smc + SB_RD);
    float* ns  = (float*)(smc + SB_NS);
    uint32_t* iq2 = (uint32_t*)(smc + SB_IQ2);
    uint32_t* ik2 = (uint32_t*)(smc + SB_IK2);
    float* scr = (float*)(smc + SB_SCR);

    int tid = threadIdx.x, wid = tid >> 5, lane = tid & 31;
    int cblk = blockIdx.x, b = blockIdx.y;
    int m0 = cblk * MPER;
    int mgrp = tid & 15, dg0 = tid >> 4;   // dg0 0..31
    int m4 = mgrp * 4;

    // ---- phase 1: single global read; norm/dot partials; raw bf16 in regs
    const float* qg = q + (size_t)b * DIM * NPTS + m0 + m4;
    const float* kg = k + (size_t)b * DIM * NPTS + m0 + m4;
    uint2 qr[4], kr[4];
    float sq0 = 0.f, sq1 = 0.f, sq2 = 0.f, sq3 = 0.f;
    float sk0 = 0.f, sk1 = 0.f, sk2 = 0.f, sk3 = 0.f;
    float dt0 = 0.f, dt1 = 0.f, dt2 = 0.f, dt3 = 0.f;
#pragma unroll
    for (int it = 0; it < 4; it++) {
        int d = dg0 + it * 32;
        float4 vq = *(const float4*)(qg + (size_t)d * NPTS);
        float4 vk = *(const float4*)(kg + (size_t)d * NPTS);
        sq0 += fabsf(vq.x); sq1 += fabsf(vq.y); sq2 += fabsf(vq.z); sq3 += fabsf(vq.w);
        sk0 += fabsf(vk.x); sk1 += fabsf(vk.y); sk2 += fabsf(vk.z); sk3 += fabsf(vk.w);
        dt0 += vq.x * vk.x; dt1 += vq.y * vk.y; dt2 += vq.z * vk.z; dt3 += vq.w * vk.w;
        qr[it] = make_uint2(bf2u(__float22bfloat162_rn(make_float2(vq.x, vq.y))),
                            bf2u(__float22bfloat162_rn(make_float2(vq.z, vq.w))));
        kr[it] = make_uint2(bf2u(__float22bfloat162_rn(make_float2(vk.x, vk.y))),
                            bf2u(__float22bfloat162_rn(make_float2(vk.z, vk.w))));
    }
    *(float4*)(rq + dg0 * 64 + m4) = make_float4(sq0, sq1, sq2, sq3);
    *(float4*)(rk + dg0 * 64 + m4) = make_float4(sk0, sk1, sk2, sk3);
    *(float4*)(rd + dg0 * 64 + m4) = make_float4(dt0, dt1, dt2, dt3);
    __syncthreads();

    // ---- phase 2a: reduce 32 dgroups for each of 64 m; 3 arrays in parallel
    if (tid < 192) {
        int arr = tid >> 6, m = tid & 63;
        const float* basep = (const float*)(smc + arr * 8192);
        float s = 0.f;
#pragma unroll
        for (int g = 0; g < 32; g++) s += basep[g * 64 + m];
        ns[arr * 64 + m] = s;
    }
    __syncthreads();

    // ---- phase 2b: inv norms, packed bf16x2 scales, dg/dg2 block totals ---
    if (tid < 64) {
        int m = tid;
        float iqv = 1.f / fmaxf(ns[m], 1e-12f);
        float ikv = 1.f / fmaxf(ns[64 + m], 1e-12f);
        float dt  = ns[128 + m];
        float iqh = __shfl_down_sync(0xffffffffu, iqv, 1);
        float ikh = __shfl_down_sync(0xffffffffu, ikv, 1);
        if ((m & 1) == 0) {
            iq2[m >> 1] = bf2u(__float22bfloat162_rn(make_float2(iqv, iqh)));
            ik2[m >> 1] = bf2u(__float22bfloat162_rn(make_float2(ikv, ikh)));
        }
        float dg = dt * iqv * ikv;
        float dg2 = dg * dg;
#pragma unroll
        for (int o = 16; o; o >>= 1) {
            dg  += __shfl_down_sync(0xffffffffu, dg, o);
            dg2 += __shfl_down_sync(0xffffffffu, dg2, o);
        }
        if (lane == 0) { scr[wid] = dg; scr[2 + wid] = dg2; }
    }
    __syncthreads();
    if (tid == 0) {
        int blk = b * MC + cblk;
        g_dgpart[blk]  = scr[0] + scr[1];
        g_dg2part[blk] = scr[2] + scr[3];
    }

    // ---- phase 3: HMUL2 normalize regs -> tiles; per-d column sums --------
    float* sqout = g_spart + ((size_t)(0 * BATCH + b) * MC + cblk) * DIM;
    float* skout = g_spart + ((size_t)(1 * BATCH + b) * MC + cblk) * DIM;
    {
        uint32_t su0 = iq2[mgrp * 2], su1 = iq2[mgrp * 2 + 1];
        uint32_t tu0 = ik2[mgrp * 2], tu1 = ik2[mgrp * 2 + 1];
#pragma unroll
        for (int it = 0; it < 4; it++) {
            int d = dg0 + it * 32;
            uint32_t q0 = hmul2u(qr[it].x, su0);
            uint32_t q1 = hmul2u(qr[it].y, su1);
            uint32_t k0 = hmul2u(kr[it].x, tu0);
            uint32_t k1 = hmul2u(kr[it].y, tu1);
            uint32_t off = (uint32_t)(d * BSTRIDE + mgrp * 8);
            *(uint2*)(qb + off) = make_uint2(q0, q1);
            *(uint2*)(kb + off) = make_uint2(k0, k1);
            float2 f0 = __bfloat1622float2(*(__nv_bfloat162*)&q0);
            float2 f1 = __bfloat1622float2(*(__nv_bfloat162*)&q1);
            float2 g0 = __bfloat1622float2(*(__nv_bfloat162*)&k0);
            float2 g1 = __bfloat1622float2(*(__nv_bfloat162*)&k1);
            float cs = (f0.x + f0.y) + (f1.x + f1.y);
            float ck = (g0.x + g0.y) + (g1.x + g1.y);
#pragma unroll
            for (int o = 8; o; o >>= 1) {
                cs += __shfl_down_sync(0xffffffffu, cs, o, 16);
                ck += __shfl_down_sync(0xffffffffu, ck, o, 16);
            }
            if (mgrp == 0) { sqout[d] = cs; skout[d] = ck; }
        }
    }
    __syncthreads();

    // ---- phase 4: two 16x64 gram jobs per warp (gram 0 then gram 1) -------
    // A row-major [d1][m] and B col-major [m][d2] share the same [d][m] tile.
    int ri = wid >> 1, jc = wid & 1;
    int grp = lane >> 3;
    uint32_t arow_off = (uint32_t)((ri * 16 + ((grp & 1) << 3) + (lane & 7)) * BSTRIDE
                                   + ((grp >> 1) << 4));
    uint32_t brow_off = (uint32_t)((jc * 64 + ((grp >> 1) << 3) + (lane & 7)) * BSTRIDE
                                   + ((grp & 1) << 4));
    int r  = lane >> 2;
    int cp = (lane & 3) << 1;
    int d1r = ri * 16 + r;

#pragma unroll
    for (int gram = 0; gram < 2; gram++) {
        uint32_t base = smem_u32(gram ? kb : qb);
        float c[32];
#pragma unroll
        for (int i = 0; i < 32; i++) c[i] = 0.f;
#pragma unroll
        for (int ks = 0; ks < 4; ks++) {
            uint32_t a[4];
            ldsm_x4(a, base + arow_off + ks * 32);
#pragma unroll
            for (int bt = 0; bt < 4; bt++) {
                uint32_t bb[4];
                ldsm_x4(bb, base + brow_off + (uint32_t)(bt * 16 * BSTRIDE) + ks * 32);
                mma_bf16(c + bt * 8,     a, bb[0], bb[1]);
                mma_bf16(c + bt * 8 + 4, a, bb[2], bb[3]);
            }
        }
        uint32_t* outp = g_gpart
            + ((size_t)(gram * BATCH + b) * MC + cblk) * 8192;  // u32 pairs
#pragma unroll
        for (int bt = 0; bt < 4; bt++) {
#pragma unroll
            for (int h = 0; h < 2; h++) {
                int col = jc * 64 + bt * 16 + h * 8 + cp;
                const float* cc = c + bt * 8 + h * 4;
                outp[(d1r * 128 + col) >> 1] =
                    bf2u(__float22bfloat162_rn(make_float2(cc[0], cc[1])));
                outp[((d1r + 8) * 128 + col) >> 1] =
                    bf2u(__float22bfloat162_rn(make_float2(cc[2], cc[3])));
            }
        }
    }
}

// ===========================================================================
// k_red: grid (33, 4). x<32: Frobenius partials from bf16 gram partials;
// x==32: s1 per batch. Last-arriving block computes the final scalar loss.
// ===========================================================================
__global__ __launch_bounds__(256) void k_red(float* __restrict__ out) {
    __shared__ float rr[8];
    __shared__ float sq[DIM], sk[DIM];
    __shared__ bool last;
    int b = blockIdx.y;
    int tid = threadIdx.x;

    if (blockIdx.x < 32) {
        int p = blockIdx.x * 256 + tid;   // bf16-pair index 0..8191
        const uint32_t* p0 = g_gpart + ((size_t)(0 * BATCH + b) * MC) * 8192 + p;
        const uint32_t* p1 = g_gpart + ((size_t)(1 * BATCH + b) * MC) * 8192 + p;
        float gqx = 0.f, gqy = 0.f, gkx = 0.f, gky = 0.f;
#pragma unroll 8
        for (int c = 0; c < MC; c++) {
            uint32_t uq = p0[(size_t)c * 8192];
            uint32_t uk = p1[(size_t)c * 8192];
            float2 fq = __bfloat1622float2(*(__nv_bfloat162*)&uq);
            float2 fk = __bfloat1622float2(*(__nv_bfloat162*)&uk);
            gqx += fq.x; gqy += fq.y; gkx += fk.x; gky += fk.y;
        }
        float f = gqx * gkx + gqy * gky;
#pragma unroll
        for (int o = 16; o; o >>= 1) f += __shfl_down_sync(0xffffffffu, f, o);
        if ((tid & 31) == 0) rr[tid >> 5] = f;
        __syncthreads();
        if (tid == 0) {
            float t = 0.f;
#pragma unroll
            for (int i = 0; i < 8; i++) t += rr[i];
            g_fpart[b * 32 + blockIdx.x] = t;
        }
    } else {
        int w = tid >> 7, d = tid & 127;
        const float* p = g_spart + ((size_t)(w * BATCH + b) * MC) * DIM + d;
        float s = 0.f;
#pragma unroll 8
        for (int c = 0; c < MC; c++) s += p[(size_t)c * DIM];
        if (w == 0) sq[d] = s; else sk[d] = s;
        __syncthreads();
        if (tid < 128) {
            float v = sq[tid] * sk[tid];
#pragma unroll
            for (int o = 16; o; o >>= 1) v += __shfl_down_sync(0xffffffffu, v, o);
            if ((tid & 31) == 0) rr[tid >> 5] = v;
        }
        __syncthreads();
        if (tid == 0) g_s1[b] = rr[0] + rr[1] + rr[2] + rr[3];
    }

    // ---- finisher: last block of the 132 computes the scalar loss --------
    __syncthreads();
    if (tid == 0) {
        __threadfence();
        last = (atomicAdd(&g_ctr, 1u) == 33 * BATCH - 1);
    }
    __syncthreads();
    if (last) {
        __shared__ float red[256];
        const float halfT2 = 0.5f * INV_T * INV_T;
        float v = 0.f;
        if (tid < BATCH * 32) v += halfT2 * g_fpart[tid];
        if (tid < BATCH)      v += INV_T * g_s1[tid];
        v -= INV_T * g_dgpart[tid] + halfT2 * g_dg2part[tid];
        red[tid] = v;
        __syncthreads();
#pragma unroll
        for (int s = 128; s; s >>= 1) {
            if (tid < s) red[tid] += red[tid + s];
            __syncthreads();
        }
        if (tid == 0) {
            out[0] = logf((float)NPTS) + red[0] / ((float)NPTS * (float)NB);
            g_ctr = 0;   // reset for next graph replay
        }
    }
}

// ===========================================================================
extern "C" void kernel_launch(void* const* d_in, const int* in_sizes, int n_in,
                              void* d_out, int out_size) {
    const float* q = (const float*)d_in[0];
    const float* k = (const float*)d_in[1];
    float* out = (float*)d_out;
    (void)in_sizes; (void)n_in; (void)out_size;

    cudaFuncSetAttribute(k_main, cudaFuncAttributeMaxDynamicSharedMemorySize,
                         SB_TOTAL);

    k_main<<<dim3(MC, BATCH), 512, SB_TOTAL>>>(q, k);
    k_red<<<dim3(33, BATCH), 256>>>(out);
}